// round 6
// baseline (speedup 1.0000x reference)
#include <cuda_runtime.h>
#include <math.h>

// x: 4096x4096 fp32 = 16,777,216 elements -> 262,144 blocks of 64.
#define MAXB   262144
#define MAXGA  8192

__device__ float  g_scales[MAXB];
__device__ float2 g_info2[MAXB];    // {1/s (RN), deq_scale}
__device__ float  g_pmin[MAXGA];
__device__ float  g_pmax[MAXGA];
__device__ float  g_smin;
__device__ float  g_ss;
__device__ int    g_cond;
__device__ unsigned g_ctr;          // last-CTA election (returns to 0 each run)

// Branchless insertion of v into descending top-5.
__device__ __forceinline__ void ins5(float v, float& t0, float& t1, float& t2,
                                     float& t3, float& t4) {
    float hi, lo;
    hi = fmaxf(t0, v); lo = fminf(t0, v); t0 = hi; v = lo;
    hi = fmaxf(t1, v); lo = fminf(t1, v); t1 = hi; v = lo;
    hi = fmaxf(t2, v); lo = fminf(t2, v); t2 = hi; v = lo;
    hi = fmaxf(t3, v); lo = fminf(t3, v); t3 = hi; v = lo;
    t4 = fmaxf(t4, v);
}

// Merge partner lane's sorted top-5 (via shfl.bfly) into mine. Progressive
// insertion: partner's b_k is <= b_{k-1}, so it can only land at level >= k.
// Cost: 5 SHFL + 25 FMNMX.
__device__ __forceinline__ void merge_bfly(int m, float& t0, float& t1,
                                           float& t2, float& t3, float& t4) {
    const unsigned FULL = 0xFFFFFFFFu;
    float b0 = __shfl_xor_sync(FULL, t0, m);
    float b1 = __shfl_xor_sync(FULL, t1, m);
    float b2 = __shfl_xor_sync(FULL, t2, m);
    float b3 = __shfl_xor_sync(FULL, t3, m);
    float b4 = __shfl_xor_sync(FULL, t4, m);
    float hi, lo, v;
    // b0: full insert (9)
    hi = fmaxf(t0, b0); lo = fminf(t0, b0); t0 = hi; v = lo;
    hi = fmaxf(t1, v);  lo = fminf(t1, v);  t1 = hi; v = lo;
    hi = fmaxf(t2, v);  lo = fminf(t2, v);  t2 = hi; v = lo;
    hi = fmaxf(t3, v);  lo = fminf(t3, v);  t3 = hi; v = lo;
    t4 = fmaxf(t4, v);
    // b1: start level 1 (7)
    hi = fmaxf(t1, b1); lo = fminf(t1, b1); t1 = hi; v = lo;
    hi = fmaxf(t2, v);  lo = fminf(t2, v);  t2 = hi; v = lo;
    hi = fmaxf(t3, v);  lo = fminf(t3, v);  t3 = hi; v = lo;
    t4 = fmaxf(t4, v);
    // b2: start level 2 (5)
    hi = fmaxf(t2, b2); lo = fminf(t2, b2); t2 = hi; v = lo;
    hi = fmaxf(t3, v);  lo = fminf(t3, v);  t3 = hi; v = lo;
    t4 = fmaxf(t4, v);
    // b3: start level 3 (3)
    hi = fmaxf(t3, b3); lo = fminf(t3, b3); t3 = hi; v = lo;
    t4 = fmaxf(t4, v);
    // b4: (1)
    t4 = fmaxf(t4, b4);
}

// ---------------------------------------------------------------------------
// Kernel A: per-block 95th-percentile scale. Barrier-free, smem-free (except
// tiny reduction arrays). 4 lanes per 64-elem block: lane L loads 4 CONSECUTIVE
// float4 (warp covers 8KB contiguous -> coalesced), builds its top-5, then two
// butterfly merges (xor1, xor2) give the block top-5 in all 4 lanes.
// Warp bfly + per-CTA + last-CTA reduction produce global scale min/max.
// ---------------------------------------------------------------------------
__global__ void __launch_bounds__(256) kA(const float4* __restrict__ in4,
                                          int n4, int num_blocks) {
    __shared__ float wmin[8], wmax[8];
    __shared__ float rmin[256], rmax[256];
    __shared__ int   s_last;

    const int tid  = threadIdx.x;
    const int lane = tid & 31;
    const int warp = tid >> 5;
    const long long gw = (long long)blockIdx.x * 8 + warp;  // global warp id
    const long long f4base = gw * 128 + lane * 4;           // 4 f4 per lane

    float4 v0, v1, v2, v3;
    {
        long long g = f4base;
        float4 z = make_float4(0.f, 0.f, 0.f, 0.f);
        v0 = (g + 0 < (long long)n4) ? in4[g + 0] : z;
        v1 = (g + 1 < (long long)n4) ? in4[g + 1] : z;
        v2 = (g + 2 < (long long)n4) ? in4[g + 2] : z;
        v3 = (g + 3 < (long long)n4) ? in4[g + 3] : z;
    }

    float t0 = 0.f, t1 = 0.f, t2 = 0.f, t3 = 0.f, t4 = 0.f;
    ins5(fabsf(v0.x), t0, t1, t2, t3, t4);
    ins5(fabsf(v0.y), t0, t1, t2, t3, t4);
    ins5(fabsf(v0.z), t0, t1, t2, t3, t4);
    ins5(fabsf(v0.w), t0, t1, t2, t3, t4);
    ins5(fabsf(v1.x), t0, t1, t2, t3, t4);
    ins5(fabsf(v1.y), t0, t1, t2, t3, t4);
    ins5(fabsf(v1.z), t0, t1, t2, t3, t4);
    ins5(fabsf(v1.w), t0, t1, t2, t3, t4);
    ins5(fabsf(v2.x), t0, t1, t2, t3, t4);
    ins5(fabsf(v2.y), t0, t1, t2, t3, t4);
    ins5(fabsf(v2.z), t0, t1, t2, t3, t4);
    ins5(fabsf(v2.w), t0, t1, t2, t3, t4);
    ins5(fabsf(v3.x), t0, t1, t2, t3, t4);
    ins5(fabsf(v3.y), t0, t1, t2, t3, t4);
    ins5(fabsf(v3.z), t0, t1, t2, t3, t4);
    ins5(fabsf(v3.w), t0, t1, t2, t3, t4);

    merge_bfly(1, t0, t1, t2, t3, t4);   // combine quarter pairs
    merge_bfly(2, t0, t1, t2, t3, t4);   // combine halves -> block top-5

    // jnp.quantile linear: index = fp32(0.95*63), frac = index - 59.
    // a[59] = 5th largest = t4, a[60] = 4th largest = t3.
    const float FRAC = 0.95f * 63.0f - 59.0f;
    const float OMF  = 1.0f - FRAC;
    float s = __fadd_rn(__fmul_rn(t4, OMF), __fmul_rn(t3, FRAC));
    s = fmaxf(s, 1e-8f);

    long long b = gw * 8 + (lane >> 2);
    bool bvalid = (b < (long long)num_blocks);
    if (bvalid && (lane & 3) == 0) g_scales[b] = s;

    // warp reduce min/max of scales (4x duplication is harmless for min/max)
    float smn = bvalid ? s : 3.402823466e38f;
    float smx = bvalid ? s : 0.0f;
    #pragma unroll
    for (int m = 16; m > 0; m >>= 1) {
        smn = fminf(smn, __shfl_xor_sync(0xFFFFFFFFu, smn, m));
        smx = fmaxf(smx, __shfl_xor_sync(0xFFFFFFFFu, smx, m));
    }
    if (lane == 0) { wmin[warp] = smn; wmax[warp] = smx; }
    __syncthreads();
    if (tid == 0) {
        float mn = wmin[0], mx = wmax[0];
        #pragma unroll
        for (int w = 1; w < 8; w++) {
            mn = fminf(mn, wmin[w]);
            mx = fmaxf(mx, wmax[w]);
        }
        __stcg(&g_pmin[blockIdx.x], mn);
        __stcg(&g_pmax[blockIdx.x], mx);
        __threadfence();
        s_last = (atomicAdd(&g_ctr, 1u) == gridDim.x - 1);
    }
    __syncthreads();

    if (s_last) {                       // CTA-uniform: final global reduce
        int np = gridDim.x;
        float mn = 3.402823466e38f, mx = 0.0f;
        for (int i = tid; i < np; i += 256) {
            mn = fminf(mn, __ldcg(&g_pmin[i]));
            mx = fmaxf(mx, __ldcg(&g_pmax[i]));
        }
        rmin[tid] = mn; rmax[tid] = mx;
        __syncthreads();
        #pragma unroll
        for (int off = 128; off > 0; off >>= 1) {
            if (tid < off) {
                rmin[tid] = fminf(rmin[tid], rmin[tid + off]);
                rmax[tid] = fmaxf(rmax[tid], rmax[tid + off]);
            }
            __syncthreads();
        }
        if (tid == 0) {
            float smin = rmin[0], smax = rmax[0];
            int cond = (smax > smin);
            g_smin = smin;
            g_cond = cond;
            g_ss = cond ? __fdiv_rn(__fsub_rn(smax, smin), 255.0f) : 1.0f;
            g_ctr = 0u;                 // reset for next graph replay
        }
    }
}

// ---------------------------------------------------------------------------
// Kernel C: per-block finalize — 8-bit double-quant of scale + RN reciprocal.
// ---------------------------------------------------------------------------
__global__ void __launch_bounds__(256) kC(int num_blocks) {
    int b = blockIdx.x * 256 + threadIdx.x;
    if (b >= num_blocks) return;
    float s = g_scales[b];
    float qv = 0.0f;
    if (g_cond) {
        qv = rintf(__fdiv_rn(__fsub_rn(s, g_smin), g_ss)); // half-even = jnp.round
        qv = fminf(fmaxf(qv, 0.0f), 255.0f);
    }
    float deq = __fmul_rn(qv, g_ss);  // smin deliberately dropped (matches ref)
    float r   = __frcp_rn(s);
    g_info2[b] = make_float2(r, deq);
}

// ---------------------------------------------------------------------------
// Kernel D: quant+dequant in one read of x (L2-resident after kA). 8 instrs
// per element via fp32 bit-grid rounding: magnitude levels {0.75,1,1.5,2,3}
// are the 1-mantissa-bit fp32 grid -> clamp |q| to [0.75,3], +0x1FFFFF
// (round-half-down = positive argmin tie rule), mask. Zero if |q|<=0.375.
// ---------------------------------------------------------------------------
__device__ __forceinline__ float qd1(float x, float r, float deq) {
    float q = __fmul_rn(x, r);
    float a = fabsf(q);
    float m = fminf(fmaxf(a, 0.75f), 3.0f);
    unsigned u = __float_as_uint(m) + 0x001FFFFFu;
    u &= 0xFFC00000u;
    float mag = (a > 0.375f) ? __uint_as_float(u) : 0.0f;
    float v = __fmul_rn(mag, deq);
    return __uint_as_float(__float_as_uint(v) |
                           (__float_as_uint(q) & 0x80000000u));
}

__global__ void __launch_bounds__(256) kD(const float4* __restrict__ in4,
                                          float4* __restrict__ out4, int n4) {
    int base = blockIdx.x * 2048 + threadIdx.x;
    #pragma unroll
    for (int k = 0; k < 8; k++) {
        int i = base + k * 256;
        if (i < n4) {
            int b = i >> 4;                 // 16 float4 per 64-elem block
            float2 nfo = g_info2[b];        // broadcast across 16 threads
            float4 x = __ldcg(&in4[i]);     // L2 hit; skip L1
            float4 o;
            o.x = qd1(x.x, nfo.x, nfo.y);
            o.y = qd1(x.y, nfo.x, nfo.y);
            o.z = qd1(x.z, nfo.x, nfo.y);
            o.w = qd1(x.w, nfo.x, nfo.y);
            __stcs(&out4[i], o);            // stream out
        }
    }
}

// Scalar tail (n % 4 != 0) — not hit for 4096x4096.
__global__ void kDtail(const float* __restrict__ in, float* __restrict__ out,
                       int start, int n) {
    int i = start + blockIdx.x * blockDim.x + threadIdx.x;
    if (i >= n) return;
    int b = i >> 6;
    float2 nfo = g_info2[b];
    out[i] = qd1(in[i], nfo.x, nfo.y);
}

extern "C" void kernel_launch(void* const* d_in, const int* in_sizes, int n_in,
                              void* d_out, int out_size) {
    const float* x = (const float*)d_in[0];
    float* out = (float*)d_out;
    int n = in_sizes[0];

    int num_blocks = (n + 63) >> 6;
    if (num_blocks > MAXB) num_blocks = MAXB;   // fixed shape fits

    // kA: 256 threads = 8 warps = 64 blocks per CTA
    int gridA = (num_blocks + 63) >> 6;
    if (gridA > MAXGA) gridA = MAXGA;
    int n4 = n >> 2;

    kA<<<gridA, 256>>>((const float4*)x, n4, num_blocks);
    kC<<<(num_blocks + 255) >> 8, 256>>>(num_blocks);
    if (n4 > 0)
        kD<<<(n4 + 2047) >> 11, 256>>>((const float4*)x, (float4*)out, n4);
    int tail = n & 3;
    if (tail)
        kDtail<<<1, 32>>>(x, out, n4 << 2, n);
}